// round 10
// baseline (speedup 1.0000x reference)
#include <cuda_runtime.h>
#include <math.h>
#include <stdint.h>

// Problem constants
#define BB   2
#define SEQ  2048
#define DMODEL 1024
#define NH   16
#define DH   64
#define BH   (BB*NH)          // 32
#define MTOT (BB*SEQ)         // 4096

#define OUT_ELEMS  ((size_t)MTOT * DMODEL)          // 4,194,304
#define ATTN_ELEMS ((size_t)BH * SEQ * SEQ)         // 134,217,728

// ---------------------------------------------------------------------------
// Scratch (static __device__ arrays: allowed; no cudaMalloc anywhere)
// ---------------------------------------------------------------------------
__device__ float g_coef[MTOT * DMODEL];     // 16 MB  sigmoid gate + 1
__device__ float g_Qb[BH * SEQ * DH];       // 16 MB  [b,h,s,d]
__device__ float g_Kb[BH * SEQ * DH];       // 16 MB
__device__ float g_Vb[BH * SEQ * DH];       // 16 MB
__device__ float g_ctx[BH * SEQ * DH];      // 16 MB
__device__ float g_rowsum[BH * SEQ];        // 256 KB
__device__ float g_Pbuf[ATTN_ELEMS];        // 536 MB fallback when attn not in d_out
__device__ int   g_mask_kind;               // 0=u8, 1=i32, 2=f32

// ---------------------------------------------------------------------------
// Mask dtype detector: bool arrays may arrive as uint8 / int32 / float32.
// Random 0/1 data: uint8 => '1' bytes at non-word-aligned positions.
// float32 1.0f  => 0x3F at byte offset %4==3.  Else int32.
// ---------------------------------------------------------------------------
__global__ void detect_mask_kind_k(const unsigned char* __restrict__ m) {
    __shared__ int odd1, f3;
    if (threadIdx.x == 0) { odd1 = 0; f3 = 0; }
    __syncthreads();
    int lo = 0, lf = 0;
    for (int i = threadIdx.x; i < 4096; i += blockDim.x) {
        unsigned char b = m[i];
        if ((i & 3) != 0 && b == 1)    lo = 1;
        if ((i & 3) == 3 && b == 0x3F) lf = 1;
    }
    if (lo) atomicOr(&odd1, 1);
    if (lf) atomicOr(&f3, 1);
    __syncthreads();
    if (threadIdx.x == 0) g_mask_kind = odd1 ? 0 : (f3 ? 2 : 1);
}

// ---------------------------------------------------------------------------
// Generic 64x64 fp32 GEMM, 256 threads, 4x4 register tiles, BK=16.
// MODE 0: coef  = 1 + sigmoid(A@W + bias)                 -> C[m*DM+n]
// MODE 1: gated projection: (A@W) * coef[m,n]             -> C in [b,h,s,d]
// MODE 2: plain projection (V)                            -> C in [b,h,s,d]
// MODE 3: out proj: A read from [b,h,s,d] ctx; += inQ     -> C[m*DM+n]
// M=4096, N=K=1024 for all modes.
// ---------------------------------------------------------------------------
template<int MODE>
__global__ void __launch_bounds__(256) gemm64_k(
    const float* __restrict__ A, const float* __restrict__ Bw,
    const float* __restrict__ aux, float* __restrict__ C)
{
    __shared__ float As[16][68];
    __shared__ float Bs[16][68];
    const int tid = threadIdx.x;
    const int m0 = blockIdx.y * 64, n0 = blockIdx.x * 64;
    const int ty = tid >> 4, tx = tid & 15;
    const int am = tid >> 2, akq = tid & 3;   // A tile loader: row am, float4 col akq
    const int bk = tid >> 4, bnq = tid & 15;  // B tile loader

    float acc[4][4] = {};

    for (int k0 = 0; k0 < DMODEL; k0 += 16) {
        float4 a4;
        if (MODE == 3) {
            int m = m0 + am;
            int b = m >> 11, s = m & (SEQ - 1);
            int kk = k0 + akq * 4;
            int h = kk >> 6, d = kk & 63;     // float4 never crosses a head boundary
            a4 = *(const float4*)&A[(((size_t)(b * NH + h)) * SEQ + s) * DH + d];
        } else {
            a4 = *(const float4*)&A[(size_t)(m0 + am) * DMODEL + k0 + akq * 4];
        }
        As[akq * 4 + 0][am] = a4.x; As[akq * 4 + 1][am] = a4.y;
        As[akq * 4 + 2][am] = a4.z; As[akq * 4 + 3][am] = a4.w;

        float4 b4 = *(const float4*)&Bw[(size_t)(k0 + bk) * DMODEL + n0 + bnq * 4];
        *(float4*)&Bs[bk][bnq * 4] = b4;
        __syncthreads();

        #pragma unroll
        for (int k = 0; k < 16; k++) {
            float4 af = *(float4*)&As[k][ty * 4];
            float4 bf = *(float4*)&Bs[k][tx * 4];
            float av[4] = {af.x, af.y, af.z, af.w};
            float bv[4] = {bf.x, bf.y, bf.z, bf.w};
            #pragma unroll
            for (int i = 0; i < 4; i++)
                #pragma unroll
                for (int j = 0; j < 4; j++)
                    acc[i][j] = fmaf(av[i], bv[j], acc[i][j]);
        }
        __syncthreads();
    }

    #pragma unroll
    for (int i = 0; i < 4; i++) {
        int m = m0 + ty * 4 + i;
        #pragma unroll
        for (int j = 0; j < 4; j++) {
            int n = n0 + tx * 4 + j;
            float v = acc[i][j];
            if (MODE == 0) {
                v += aux[n];                               // We_b
                v = 1.0f + 1.0f / (1.0f + __expf(-v));     // sigmoid + 1
                C[(size_t)m * DMODEL + n] = v;
            } else if (MODE == 1 || MODE == 2) {
                if (MODE == 1) v *= aux[(size_t)m * DMODEL + n];  // coef gate
                int b = m >> 11, s = m & (SEQ - 1);
                int h = n >> 6, d = n & 63;
                C[(((size_t)(b * NH + h)) * SEQ + s) * DH + d] = v;
            } else { // MODE 3
                v += aux[(size_t)m * DMODEL + n];          // residual input_Q
                C[(size_t)m * DMODEL + n] = v;
            }
        }
    }
}

// ---------------------------------------------------------------------------
// Pass 1: P = exp(mask ? -inf : dist * (Q.K)/8), unnormalized; rowsum per s.
// Block = (h, s_tile, b); computes 64 rows x all 2048 cols.
// No-max softmax: scores bounded ~|10| -> exp safe in fp32; masked -> 0.
// ---------------------------------------------------------------------------
__global__ void __launch_bounds__(256) attn_scores_k(
    const float* __restrict__ Q, const float* __restrict__ Kx,
    const float* __restrict__ dist, const void* __restrict__ mask,
    float* __restrict__ P, float* __restrict__ rowsum)
{
    __shared__ float Qs[64][68];
    __shared__ float Ks[64][68];
    const int tid = threadIdx.x;
    const int h = blockIdx.x, st = blockIdx.y, b = blockIdx.z;
    const int bh = b * NH + h;
    const int s0 = st * 64;
    const int kind = g_mask_kind;

    // Load Q tile [64 rows x 64 dims], store k-major with pad
    const size_t qbase = ((size_t)bh * SEQ + s0) * DH;
    #pragma unroll
    for (int i = 0; i < 4; i++) {
        int idx = tid + i * 256;
        int row = idx >> 4, c4 = idx & 15;
        float4 q4 = *(const float4*)&Q[qbase + (size_t)row * DH + c4 * 4];
        Qs[c4 * 4 + 0][row] = q4.x; Qs[c4 * 4 + 1][row] = q4.y;
        Qs[c4 * 4 + 2][row] = q4.z; Qs[c4 * 4 + 3][row] = q4.w;
    }

    const int ty = tid >> 4, tx = tid & 15;
    float rowacc[4] = {0.f, 0.f, 0.f, 0.f};
    const unsigned char* m8  = (const unsigned char*)mask;
    const int*           m32 = (const int*)mask;
    const float*         mf  = (const float*)mask;

    for (int t0 = 0; t0 < SEQ; t0 += 64) {
        __syncthreads();  // previous tile's compute done (also covers Qs init)
        const size_t kbase = ((size_t)bh * SEQ + t0) * DH;
        #pragma unroll
        for (int i = 0; i < 4; i++) {
            int idx = tid + i * 256;
            int row = idx >> 4, c4 = idx & 15;
            float4 k4 = *(const float4*)&Kx[kbase + (size_t)row * DH + c4 * 4];
            Ks[c4 * 4 + 0][row] = k4.x; Ks[c4 * 4 + 1][row] = k4.y;
            Ks[c4 * 4 + 2][row] = k4.z; Ks[c4 * 4 + 3][row] = k4.w;
        }
        __syncthreads();

        float acc[4][4] = {};
        #pragma unroll
        for (int k = 0; k < 64; k++) {
            float4 af = *(float4*)&Qs[k][ty * 4];
            float4 bf = *(float4*)&Ks[k][tx * 4];
            float av[4] = {af.x, af.y, af.z, af.w};
            float bv[4] = {bf.x, bf.y, bf.z, bf.w};
            #pragma unroll
            for (int i = 0; i < 4; i++)
                #pragma unroll
                for (int j = 0; j < 4; j++)
                    acc[i][j] = fmaf(av[i], bv[j], acc[i][j]);
        }

        #pragma unroll
        for (int i = 0; i < 4; i++) {
            int s = s0 + ty * 4 + i;
            size_t drow = ((size_t)b * SEQ + s) * SEQ;
            size_t prow = ((size_t)bh * SEQ + s) * SEQ;
            #pragma unroll
            for (int j = 0; j < 4; j++) {
                int t = t0 + tx * 4 + j;
                float sc = acc[i][j] * 0.125f * dist[drow + t];
                bool mk;
                if (kind == 0)      mk = (m8[drow + t] != 0);
                else if (kind == 1) mk = (m32[drow + t] != 0);
                else                mk = (mf[drow + t] != 0.0f);
                float p = mk ? 0.0f : __expf(sc);
                P[prow + t] = p;
                rowacc[i] += p;
            }
        }
    }

    // Reduce row sums across the 16 tx lanes (stay within half-warp groups)
    #pragma unroll
    for (int i = 0; i < 4; i++) {
        float v = rowacc[i];
        v += __shfl_xor_sync(0xffffffffu, v, 1);
        v += __shfl_xor_sync(0xffffffffu, v, 2);
        v += __shfl_xor_sync(0xffffffffu, v, 4);
        v += __shfl_xor_sync(0xffffffffu, v, 8);
        if (tx == 0) rowsum[(size_t)bh * SEQ + s0 + ty * 4 + i] = v;
    }
}

// ---------------------------------------------------------------------------
// Pass 2: normalize P in place (optional writeback) and ctx = Pn @ V.
// ---------------------------------------------------------------------------
__global__ void __launch_bounds__(256) attn_pv_k(
    float* __restrict__ P, const float* __restrict__ V,
    const float* __restrict__ rowsum, float* __restrict__ ctx, int writeback)
{
    __shared__ float Ps[64][68];   // [t][s]
    __shared__ float Vs[64][68];   // [t][d]
    __shared__ float invs[64];
    const int tid = threadIdx.x;
    const int h = blockIdx.x, st = blockIdx.y, b = blockIdx.z;
    const int bh = b * NH + h;
    const int s0 = st * 64;

    if (tid < 64) invs[tid] = 1.0f / rowsum[(size_t)bh * SEQ + s0 + tid];

    const int ty = tid >> 4, tx = tid & 15;
    float acc[4][4] = {};

    for (int t0 = 0; t0 < SEQ; t0 += 64) {
        __syncthreads();  // covers invs init + previous tile compute
        #pragma unroll
        for (int i = 0; i < 4; i++) {
            int idx = tid + i * 256;
            int row = idx >> 4, c4 = idx & 15;   // row = s offset, c4 = t float4
            size_t off = ((size_t)bh * SEQ + s0 + row) * SEQ + t0 + c4 * 4;
            float4 p4 = *(const float4*)&P[off];
            float inv = invs[row];
            p4.x *= inv; p4.y *= inv; p4.z *= inv; p4.w *= inv;
            if (writeback) *(float4*)&P[off] = p4;
            Ps[c4 * 4 + 0][row] = p4.x; Ps[c4 * 4 + 1][row] = p4.y;
            Ps[c4 * 4 + 2][row] = p4.z; Ps[c4 * 4 + 3][row] = p4.w;
        }
        const size_t vbase = ((size_t)bh * SEQ + t0) * DH;
        #pragma unroll
        for (int i = 0; i < 4; i++) {
            int idx = tid + i * 256;
            int row = idx >> 4, c4 = idx & 15;   // row = t, c4 = d float4
            float4 v4 = *(const float4*)&V[vbase + (size_t)row * DH + c4 * 4];
            *(float4*)&Vs[row][c4 * 4] = v4;
        }
        __syncthreads();

        #pragma unroll
        for (int k = 0; k < 64; k++) {
            float4 af = *(float4*)&Ps[k][ty * 4];
            float4 bf = *(float4*)&Vs[k][tx * 4];
            float av[4] = {af.x, af.y, af.z, af.w};
            float bv[4] = {bf.x, bf.y, bf.z, bf.w};
            #pragma unroll
            for (int i = 0; i < 4; i++)
                #pragma unroll
                for (int j = 0; j < 4; j++)
                    acc[i][j] = fmaf(av[i], bv[j], acc[i][j]);
        }
    }

    #pragma unroll
    for (int i = 0; i < 4; i++) {
        int s = s0 + ty * 4 + i;
        #pragma unroll
        for (int j = 0; j < 4; j++) {
            int d = tx * 4 + j;
            ctx[((size_t)bh * SEQ + s) * DH + d] = acc[i][j];
        }
    }
}

// ---------------------------------------------------------------------------
// Launch
// ---------------------------------------------------------------------------
extern "C" void kernel_launch(void* const* d_in, const int* in_sizes, int n_in,
                              void* d_out, int out_size)
{
    const float* inQ   = (const float*)d_in[0];
    const float* inK   = (const float*)d_in[1];
    const float* inV   = (const float*)d_in[2];
    const float* inter = (const float*)d_in[3];
    const float* dist  = (const float*)d_in[4];
    const void*  mask  = d_in[5];
    const float* W_Q   = (const float*)d_in[6];
    const float* W_K   = (const float*)d_in[7];
    const float* W_V   = (const float*)d_in[8];
    const float* W_fc  = (const float*)d_in[9];
    const float* We_w  = (const float*)d_in[10];
    const float* We_b  = (const float*)d_in[11];
    float* out = (float*)d_out;

    void *coefp_, *qp_, *kp_, *vp_, *ctxp_, *rsp_, *pbuf_;
    cudaGetSymbolAddress(&coefp_, g_coef);
    cudaGetSymbolAddress(&qp_,    g_Qb);
    cudaGetSymbolAddress(&kp_,    g_Kb);
    cudaGetSymbolAddress(&vp_,    g_Vb);
    cudaGetSymbolAddress(&ctxp_,  g_ctx);
    cudaGetSymbolAddress(&rsp_,   g_rowsum);
    cudaGetSymbolAddress(&pbuf_,  g_Pbuf);
    float* coefp = (float*)coefp_;
    float* Qp    = (float*)qp_;
    float* Kp    = (float*)kp_;
    float* Vp    = (float*)vp_;
    float* ctxp  = (float*)ctxp_;
    float* rsp   = (float*)rsp_;

    const bool need_attn = ((size_t)out_size >= OUT_ELEMS + ATTN_ELEMS);
    float* P = need_attn ? (out + OUT_ELEMS) : (float*)pbuf_;

    dim3 thr(256);
    dim3 gemm_grid(DMODEL / 64, MTOT / 64);   // (16, 64)
    dim3 attn_grid(NH, SEQ / 64, BB);         // (16, 32, 2) — heads fastest for dist L2 reuse

    detect_mask_kind_k<<<1, 256>>>((const unsigned char*)mask);

    gemm64_k<0><<<gemm_grid, thr>>>(inter, We_w, We_b, coefp);   // coef
    gemm64_k<1><<<gemm_grid, thr>>>(inQ,   W_Q,  coefp, Qp);     // Q = coef * (inQ @ W_Q)
    gemm64_k<1><<<gemm_grid, thr>>>(inK,   W_K,  coefp, Kp);     // K = coef * (inK @ W_K)
    gemm64_k<2><<<gemm_grid, thr>>>(inV,   W_V,  nullptr, Vp);   // V

    attn_scores_k<<<attn_grid, thr>>>(Qp, Kp, dist, mask, P, rsp);
    attn_pv_k<<<attn_grid, thr>>>(P, Vp, rsp, ctxp, need_attn ? 1 : 0);

    gemm64_k<3><<<gemm_grid, thr>>>(ctxp, W_fc, inQ, out);       // out = ctx @ W_fc + inQ
}

// round 11
// speedup vs baseline: 1.0171x; 1.0171x over previous
#include <cuda_runtime.h>
#include <math.h>
#include <stdint.h>

// Problem constants
#define BB   2
#define SEQ  2048
#define DMODEL 1024
#define NH   16
#define DH   64
#define BH   (BB*NH)          // 32
#define MTOT (BB*SEQ)         // 4096

#define OUT_ELEMS  ((size_t)MTOT * DMODEL)          // 4,194,304
#define ATTN_ELEMS ((size_t)BH * SEQ * SEQ)         // 134,217,728

typedef unsigned long long u64;

// ---------------------------------------------------------------------------
// Packed fp32x2 FMA helpers (FFMA2 — exact fp32, 2x FFMA throughput)
// ---------------------------------------------------------------------------
__device__ __forceinline__ u64 pk2(float lo, float hi) {
    u64 r; asm("mov.b64 %0, {%1, %2};" : "=l"(r) : "f"(lo), "f"(hi)); return r;
}
__device__ __forceinline__ u64 dup2(float v) {
    u64 r; asm("mov.b64 %0, {%1, %1};" : "=l"(r) : "f"(v)); return r;
}
__device__ __forceinline__ void fma2(u64& d, u64 a, u64 b) {
    asm("fma.rn.f32x2 %0, %1, %2, %0;" : "+l"(d) : "l"(a), "l"(b));
}
__device__ __forceinline__ float2 up2(u64 v) {
    float2 r; asm("mov.b64 {%0, %1}, %2;" : "=f"(r.x), "=f"(r.y) : "l"(v)); return r;
}
__device__ __forceinline__ float4 up4(u64 p0, u64 p1) {
    float2 a = up2(p0), b = up2(p1);
    return make_float4(a.x, a.y, b.x, b.y);
}

// 8x8 packed FMA micro-step: A-frag rows {oa0..+3, oa1..+3}, B-frag cols
// {ob0..+3, ob1..+3}; acc[8][4] of f32x2 pairs.
#define FMA8x8(ASP, BSP, OA0, OA1, OB0, OB1, ACC) do {                        \
    float4 _aA = *(const float4*)&(ASP)[(OA0)];                               \
    float4 _aB = *(const float4*)&(ASP)[(OA1)];                               \
    float4 _bA = *(const float4*)&(BSP)[(OB0)];                               \
    float4 _bB = *(const float4*)&(BSP)[(OB1)];                               \
    u64 _b0 = pk2(_bA.x,_bA.y), _b1 = pk2(_bA.z,_bA.w);                       \
    u64 _b2 = pk2(_bB.x,_bB.y), _b3 = pk2(_bB.z,_bB.w);                       \
    float _av[8] = {_aA.x,_aA.y,_aA.z,_aA.w,_aB.x,_aB.y,_aB.z,_aB.w};         \
    _Pragma("unroll")                                                         \
    for (int _i = 0; _i < 8; _i++) {                                          \
        u64 _ai = dup2(_av[_i]);                                              \
        fma2((ACC)[_i][0], _ai, _b0); fma2((ACC)[_i][1], _ai, _b1);           \
        fma2((ACC)[_i][2], _ai, _b2); fma2((ACC)[_i][3], _ai, _b3);           \
    }                                                                         \
} while (0)

// ---------------------------------------------------------------------------
// Scratch
// ---------------------------------------------------------------------------
__device__ float g_coef[MTOT * DMODEL];
__device__ float g_Qb[BH * SEQ * DH];
__device__ float g_Kb[BH * SEQ * DH];
__device__ float g_Vb[BH * SEQ * DH];
__device__ float g_ctx[BH * SEQ * DH];
__device__ float g_rowsum[BH * SEQ];
__device__ float g_Pbuf[ATTN_ELEMS];
__device__ int   g_mask_kind;   // 0=u8, 1=i32, 2=f32

// ---------------------------------------------------------------------------
// Mask dtype detector
// ---------------------------------------------------------------------------
__global__ void detect_mask_kind_k(const unsigned char* __restrict__ m) {
    __shared__ int odd1, f3;
    if (threadIdx.x == 0) { odd1 = 0; f3 = 0; }
    __syncthreads();
    int lo = 0, lf = 0;
    for (int i = threadIdx.x; i < 4096; i += blockDim.x) {
        unsigned char b = m[i];
        if ((i & 3) != 0 && b == 1)    lo = 1;
        if ((i & 3) == 3 && b == 0x3F) lf = 1;
    }
    if (lo) atomicOr(&odd1, 1);
    if (lf) atomicOr(&f3, 1);
    __syncthreads();
    if (threadIdx.x == 0) g_mask_kind = odd1 ? 0 : (f3 ? 2 : 1);
}

// ---------------------------------------------------------------------------
// 128x128 fp32 GEMM, 256 threads, 8x8 tiles (FFMA2), BK=16.
// MODE 0: coef = 1 + sigmoid(A@W + bias)
// MODE 1: (A@W) * coef -> [b,h,s,d]
// MODE 2: plain projection -> [b,h,s,d]
// MODE 3: A from [b,h,s,d] ctx; out = A@W + residual
// ---------------------------------------------------------------------------
template<int MODE>
__global__ void __launch_bounds__(256, 2) gemm128_k(
    const float* __restrict__ A, const float* __restrict__ Bw,
    const float* __restrict__ aux, float* __restrict__ C)
{
    __shared__ float As[16][132];
    __shared__ float Bs[16][132];
    const int tid = threadIdx.x;
    const int m0 = blockIdx.y * 128, n0 = blockIdx.x * 128;
    const int ty = tid >> 4, tx = tid & 15;

    u64 acc[8][4] = {};

    for (int k0 = 0; k0 < DMODEL; k0 += 16) {
        // A tile: 128 rows x 16 k, stored transposed As[k][m]
        #pragma unroll
        for (int i = 0; i < 2; i++) {
            int idx = tid + i * 256;
            int row = idx >> 2, kq = idx & 3;
            float4 a4;
            if (MODE == 3) {
                int m = m0 + row;
                int b = m >> 11, s = m & (SEQ - 1);
                int kk = k0 + kq * 4;
                int h = kk >> 6, d = kk & 63;
                a4 = *(const float4*)&A[(((size_t)(b * NH + h)) * SEQ + s) * DH + d];
            } else {
                a4 = *(const float4*)&A[(size_t)(m0 + row) * DMODEL + k0 + kq * 4];
            }
            As[kq * 4 + 0][row] = a4.x; As[kq * 4 + 1][row] = a4.y;
            As[kq * 4 + 2][row] = a4.z; As[kq * 4 + 3][row] = a4.w;
        }
        // B tile: 16 k x 128 n, direct
        #pragma unroll
        for (int i = 0; i < 2; i++) {
            int idx = tid + i * 256;
            int kk = idx >> 5, nq = idx & 31;
            *(float4*)&Bs[kk][nq * 4] =
                *(const float4*)&Bw[(size_t)(k0 + kk) * DMODEL + n0 + nq * 4];
        }
        __syncthreads();

        #pragma unroll
        for (int k = 0; k < 16; k++)
            FMA8x8(As[k], Bs[k], ty * 4, 64 + ty * 4, tx * 4, 64 + tx * 4, acc);
        __syncthreads();
    }

    // Epilogue: rows {ty*4+i, 64+ty*4+i}, col groups {tx*4, 64+tx*4}
    #pragma unroll
    for (int i = 0; i < 8; i++) {
        int m = m0 + ((i < 4) ? ty * 4 + i : 64 + ty * 4 + (i - 4));
        #pragma unroll
        for (int jg = 0; jg < 2; jg++) {
            int n = n0 + jg * 64 + tx * 4;
            float4 v = up4(acc[i][jg * 2], acc[i][jg * 2 + 1]);
            if (MODE == 0) {
                float4 bb = *(const float4*)&aux[n];
                v.x = 1.0f + 1.0f / (1.0f + __expf(-(v.x + bb.x)));
                v.y = 1.0f + 1.0f / (1.0f + __expf(-(v.y + bb.y)));
                v.z = 1.0f + 1.0f / (1.0f + __expf(-(v.z + bb.z)));
                v.w = 1.0f + 1.0f / (1.0f + __expf(-(v.w + bb.w)));
                *(float4*)&C[(size_t)m * DMODEL + n] = v;
            } else if (MODE == 1 || MODE == 2) {
                if (MODE == 1) {
                    float4 cf = *(const float4*)&aux[(size_t)m * DMODEL + n];
                    v.x *= cf.x; v.y *= cf.y; v.z *= cf.z; v.w *= cf.w;
                }
                int b = m >> 11, s = m & (SEQ - 1);
                int h = n >> 6, d = n & 63;   // 4 consecutive d within one head
                *(float4*)&C[(((size_t)(b * NH + h)) * SEQ + s) * DH + d] = v;
            } else { // MODE 3
                float4 r = *(const float4*)&aux[(size_t)m * DMODEL + n];
                v.x += r.x; v.y += r.y; v.z += r.z; v.w += r.w;
                *(float4*)&C[(size_t)m * DMODEL + n] = v;
            }
        }
    }
}

// ---------------------------------------------------------------------------
// Pass 1: P = exp(mask ? -inf : dist * (Q.K)/8) unnormalized, + rowsums.
// Block: 128 s-rows x full 2048 t; 128x128 score tiles, d chunked by 16.
// ---------------------------------------------------------------------------
__global__ void __launch_bounds__(256, 2) attn_scores_k(
    const float* __restrict__ Q, const float* __restrict__ Kx,
    const float* __restrict__ dist, const void* __restrict__ mask,
    float* __restrict__ P, float* __restrict__ rowsum)
{
    __shared__ float Qs[16][132];
    __shared__ float Ks[16][132];
    const int tid = threadIdx.x;
    const int h = blockIdx.x, st = blockIdx.y, b = blockIdx.z;
    const int bh = b * NH + h;
    const int s0 = st * 128;
    const int kind = g_mask_kind;
    const int ty = tid >> 4, tx = tid & 15;

    float rowacc[8] = {};

    const unsigned char* m8 = (const unsigned char*)mask;
    const int*           mi = (const int*)mask;
    const float*         mf = (const float*)mask;

    for (int t0 = 0; t0 < SEQ; t0 += 128) {
        u64 acc[8][4] = {};

        for (int dc = 0; dc < DH; dc += 16) {
            #pragma unroll
            for (int i = 0; i < 2; i++) {
                int idx = tid + i * 256;
                int row = idx >> 2, kq = idx & 3;
                float4 q4 = *(const float4*)&Q[((size_t)bh * SEQ + s0 + row) * DH + dc + kq * 4];
                Qs[kq * 4 + 0][row] = q4.x; Qs[kq * 4 + 1][row] = q4.y;
                Qs[kq * 4 + 2][row] = q4.z; Qs[kq * 4 + 3][row] = q4.w;
                float4 k4 = *(const float4*)&Kx[((size_t)bh * SEQ + t0 + row) * DH + dc + kq * 4];
                Ks[kq * 4 + 0][row] = k4.x; Ks[kq * 4 + 1][row] = k4.y;
                Ks[kq * 4 + 2][row] = k4.z; Ks[kq * 4 + 3][row] = k4.w;
            }
            __syncthreads();
            #pragma unroll
            for (int k = 0; k < 16; k++)
                FMA8x8(Qs[k], Ks[k], ty * 4, 64 + ty * 4, tx * 4, 64 + tx * 4, acc);
            __syncthreads();
        }

        #pragma unroll
        for (int i = 0; i < 8; i++) {
            int s = s0 + ((i < 4) ? ty * 4 + i : 64 + ty * 4 + (i - 4));
            size_t drow = ((size_t)b * SEQ + s) * SEQ;
            size_t prow = ((size_t)bh * SEQ + s) * SEQ;
            #pragma unroll
            for (int jg = 0; jg < 2; jg++) {
                int t = t0 + jg * 64 + tx * 4;
                float4 sc = up4(acc[i][jg * 2], acc[i][jg * 2 + 1]);
                float4 d4 = *(const float4*)&dist[drow + t];
                sc.x *= 0.125f * d4.x; sc.y *= 0.125f * d4.y;
                sc.z *= 0.125f * d4.z; sc.w *= 0.125f * d4.w;
                bool k0b, k1b, k2b, k3b;
                if (kind == 0) {
                    uchar4 mc = *(const uchar4*)&m8[drow + t];
                    k0b = mc.x; k1b = mc.y; k2b = mc.z; k3b = mc.w;
                } else if (kind == 1) {
                    int4 mc = *(const int4*)&mi[drow + t];
                    k0b = mc.x; k1b = mc.y; k2b = mc.z; k3b = mc.w;
                } else {
                    float4 mc = *(const float4*)&mf[drow + t];
                    k0b = mc.x != 0.0f; k1b = mc.y != 0.0f;
                    k2b = mc.z != 0.0f; k3b = mc.w != 0.0f;
                }
                float4 p;
                p.x = k0b ? 0.0f : __expf(sc.x);
                p.y = k1b ? 0.0f : __expf(sc.y);
                p.z = k2b ? 0.0f : __expf(sc.z);
                p.w = k3b ? 0.0f : __expf(sc.w);
                *(float4*)&P[prow + t] = p;
                rowacc[i] += p.x + p.y + p.z + p.w;
            }
        }
    }

    #pragma unroll
    for (int i = 0; i < 8; i++) {
        float v = rowacc[i];
        v += __shfl_xor_sync(0xffffffffu, v, 1);
        v += __shfl_xor_sync(0xffffffffu, v, 2);
        v += __shfl_xor_sync(0xffffffffu, v, 4);
        v += __shfl_xor_sync(0xffffffffu, v, 8);
        if (tx == 0) {
            int s = s0 + ((i < 4) ? ty * 4 + i : 64 + ty * 4 + (i - 4));
            rowsum[(size_t)bh * SEQ + s] = v;
        }
    }
}

// ---------------------------------------------------------------------------
// Pass 2: normalize P (optional writeback) and ctx = Pn @ V.
// Block: 256 s-rows x 64 d, t chunked by 16; 8x8 tiles (FFMA2).
// ---------------------------------------------------------------------------
__global__ void __launch_bounds__(256, 2) attn_pv_k(
    float* __restrict__ P, const float* __restrict__ V,
    const float* __restrict__ rowsum, float* __restrict__ ctx, int writeback)
{
    __shared__ float Ps[16][260];   // [t][s]
    __shared__ float Vs[16][68];    // [t][d]
    __shared__ float invs[256];
    const int tid = threadIdx.x;
    const int h = blockIdx.x, st = blockIdx.y, b = blockIdx.z;
    const int bh = b * NH + h;
    const int s0 = st * 256;
    const int ty = tid >> 3, tx = tid & 7;

    invs[tid] = 1.0f / rowsum[(size_t)bh * SEQ + s0 + tid];
    __syncthreads();

    u64 acc[8][4] = {};

    for (int t0 = 0; t0 < SEQ; t0 += 16) {
        // P chunk: 256 s x 16 t, normalize on load, transpose to Ps[t][s]
        #pragma unroll
        for (int i = 0; i < 4; i++) {
            int idx = tid + i * 256;
            int row = idx >> 2, tq = idx & 3;
            size_t off = ((size_t)bh * SEQ + s0 + row) * SEQ + t0 + tq * 4;
            float4 p4 = *(const float4*)&P[off];
            float inv = invs[row];
            p4.x *= inv; p4.y *= inv; p4.z *= inv; p4.w *= inv;
            if (writeback) *(float4*)&P[off] = p4;
            Ps[tq * 4 + 0][row] = p4.x; Ps[tq * 4 + 1][row] = p4.y;
            Ps[tq * 4 + 2][row] = p4.z; Ps[tq * 4 + 3][row] = p4.w;
        }
        // V chunk: 16 t x 64 d
        {
            int kk = tid >> 4, dq = tid & 15;
            *(float4*)&Vs[kk][dq * 4] =
                *(const float4*)&V[((size_t)bh * SEQ + t0 + kk) * DH + dq * 4];
        }
        __syncthreads();

        #pragma unroll
        for (int k = 0; k < 16; k++)
            FMA8x8(Ps[k], Vs[k], ty * 4, 128 + ty * 4, tx * 4, 32 + tx * 4, acc);
        __syncthreads();
    }

    #pragma unroll
    for (int i = 0; i < 8; i++) {
        int s = s0 + ((i < 4) ? ty * 4 + i : 128 + ty * 4 + (i - 4));
        #pragma unroll
        for (int jg = 0; jg < 2; jg++) {
            int d = jg * 32 + tx * 4;
            float4 v = up4(acc[i][jg * 2], acc[i][jg * 2 + 1]);
            *(float4*)&ctx[((size_t)bh * SEQ + s) * DH + d] = v;
        }
    }
}

// ---------------------------------------------------------------------------
// Launch
// ---------------------------------------------------------------------------
extern "C" void kernel_launch(void* const* d_in, const int* in_sizes, int n_in,
                              void* d_out, int out_size)
{
    const float* inQ   = (const float*)d_in[0];
    const float* inK   = (const float*)d_in[1];
    const float* inV   = (const float*)d_in[2];
    const float* inter = (const float*)d_in[3];
    const float* dist  = (const float*)d_in[4];
    const void*  mask  = d_in[5];
    const float* W_Q   = (const float*)d_in[6];
    const float* W_K   = (const float*)d_in[7];
    const float* W_V   = (const float*)d_in[8];
    const float* W_fc  = (const float*)d_in[9];
    const float* We_w  = (const float*)d_in[10];
    const float* We_b  = (const float*)d_in[11];
    float* out = (float*)d_out;

    void *coefp_, *qp_, *kp_, *vp_, *ctxp_, *rsp_, *pbuf_;
    cudaGetSymbolAddress(&coefp_, g_coef);
    cudaGetSymbolAddress(&qp_,    g_Qb);
    cudaGetSymbolAddress(&kp_,    g_Kb);
    cudaGetSymbolAddress(&vp_,    g_Vb);
    cudaGetSymbolAddress(&ctxp_,  g_ctx);
    cudaGetSymbolAddress(&rsp_,   g_rowsum);
    cudaGetSymbolAddress(&pbuf_,  g_Pbuf);
    float* coefp = (float*)coefp_;
    float* Qp    = (float*)qp_;
    float* Kp    = (float*)kp_;
    float* Vp    = (float*)vp_;
    float* ctxp  = (float*)ctxp_;
    float* rsp   = (float*)rsp_;

    const bool need_attn = ((size_t)out_size >= OUT_ELEMS + ATTN_ELEMS);
    float* P = need_attn ? (out + OUT_ELEMS) : (float*)pbuf_;

    dim3 thr(256);
    dim3 gemm_grid(DMODEL / 128, MTOT / 128);     // (8, 32)
    dim3 sc_grid(NH, SEQ / 128, BB);              // (16, 16, 2)
    dim3 pv_grid(NH, SEQ / 256, BB);              // (16, 8, 2)

    detect_mask_kind_k<<<1, 256>>>((const unsigned char*)mask);

    gemm128_k<0><<<gemm_grid, thr>>>(inter, We_w, We_b, coefp);
    gemm128_k<1><<<gemm_grid, thr>>>(inQ,   W_Q,  coefp, Qp);
    gemm128_k<1><<<gemm_grid, thr>>>(inK,   W_K,  coefp, Kp);
    gemm128_k<2><<<gemm_grid, thr>>>(inV,   W_V,  nullptr, Vp);

    attn_scores_k<<<sc_grid, thr>>>(Qp, Kp, dist, mask, P, rsp);
    attn_pv_k<<<pv_grid, thr>>>(P, Vp, rsp, ctxp, need_attn ? 1 : 0);

    gemm128_k<3><<<gemm_grid, thr>>>(ctxp, W_fc, inQ, out);
}

// round 12
// speedup vs baseline: 1.0206x; 1.0034x over previous
#include <cuda_runtime.h>
#include <math.h>
#include <stdint.h>

// Problem constants
#define BB   2
#define SEQ  2048
#define DMODEL 1024
#define NH   16
#define DH   64
#define BH   (BB*NH)          // 32
#define MTOT (BB*SEQ)         // 4096

#define OUT_ELEMS  ((size_t)MTOT * DMODEL)          // 4,194,304
#define ATTN_ELEMS ((size_t)BH * SEQ * SEQ)         // 134,217,728

typedef unsigned long long u64;

// ---------------------------------------------------------------------------
// Packed fp32x2 FMA helpers (FFMA2 — exact fp32, 2x FFMA throughput)
// ---------------------------------------------------------------------------
__device__ __forceinline__ u64 pk2(float lo, float hi) {
    u64 r; asm("mov.b64 %0, {%1, %2};" : "=l"(r) : "f"(lo), "f"(hi)); return r;
}
__device__ __forceinline__ u64 dup2(float v) {
    u64 r; asm("mov.b64 %0, {%1, %1};" : "=l"(r) : "f"(v)); return r;
}
__device__ __forceinline__ void fma2(u64& d, u64 a, u64 b) {
    asm("fma.rn.f32x2 %0, %1, %2, %0;" : "+l"(d) : "l"(a), "l"(b));
}
__device__ __forceinline__ float2 up2(u64 v) {
    float2 r; asm("mov.b64 {%0, %1}, %2;" : "=f"(r.x), "=f"(r.y) : "l"(v)); return r;
}
__device__ __forceinline__ float4 up4(u64 p0, u64 p1) {
    float2 a = up2(p0), b = up2(p1);
    return make_float4(a.x, a.y, b.x, b.y);
}

// 8x8 packed FMA micro-step: A-frag rows {oa0..+3, oa1..+3}, B-frag cols
// {ob0..+3, ob1..+3}; acc[8][4] of f32x2 pairs.
#define FMA8x8(ASP, BSP, OA0, OA1, OB0, OB1, ACC) do {                        \
    float4 _aA = *(const float4*)&(ASP)[(OA0)];                               \
    float4 _aB = *(const float4*)&(ASP)[(OA1)];                               \
    float4 _bA = *(const float4*)&(BSP)[(OB0)];                               \
    float4 _bB = *(const float4*)&(BSP)[(OB1)];                               \
    u64 _b0 = pk2(_bA.x,_bA.y), _b1 = pk2(_bA.z,_bA.w);                       \
    u64 _b2 = pk2(_bB.x,_bB.y), _b3 = pk2(_bB.z,_bB.w);                       \
    float _av[8] = {_aA.x,_aA.y,_aA.z,_aA.w,_aB.x,_aB.y,_aB.z,_aB.w};         \
    _Pragma("unroll")                                                         \
    for (int _i = 0; _i < 8; _i++) {                                          \
        u64 _ai = dup2(_av[_i]);                                              \
        fma2((ACC)[_i][0], _ai, _b0); fma2((ACC)[_i][1], _ai, _b1);           \
        fma2((ACC)[_i][2], _ai, _b2); fma2((ACC)[_i][3], _ai, _b3);           \
    }                                                                         \
} while (0)

// ---------------------------------------------------------------------------
// Scratch
// ---------------------------------------------------------------------------
__device__ float g_coef[MTOT * DMODEL];
__device__ float g_Qb[BH * SEQ * DH];
__device__ float g_Kb[BH * SEQ * DH];
__device__ float g_Vb[BH * SEQ * DH];
__device__ float g_ctx[BH * SEQ * DH];
__device__ float g_rowsum[BH * SEQ];
__device__ float g_Pbuf[ATTN_ELEMS];
__device__ int   g_mask_kind;   // 0=u8, 1=i32, 2=f32

// ---------------------------------------------------------------------------
// Mask dtype detector
// ---------------------------------------------------------------------------
__global__ void detect_mask_kind_k(const unsigned char* __restrict__ m) {
    __shared__ int odd1, f3;
    if (threadIdx.x == 0) { odd1 = 0; f3 = 0; }
    __syncthreads();
    int lo = 0, lf = 0;
    for (int i = threadIdx.x; i < 4096; i += blockDim.x) {
        unsigned char b = m[i];
        if ((i & 3) != 0 && b == 1)    lo = 1;
        if ((i & 3) == 3 && b == 0x3F) lf = 1;
    }
    if (lo) atomicOr(&odd1, 1);
    if (lf) atomicOr(&f3, 1);
    __syncthreads();
    if (threadIdx.x == 0) g_mask_kind = odd1 ? 0 : (f3 ? 2 : 1);
}

// ---------------------------------------------------------------------------
// 128x128 fp32 GEMM, 256 threads, 8x8 tiles (FFMA2), BK=16.
// MODE 0: coef = 1 + sigmoid(A@W + bias)
// MODE 1: (A@W) * coef -> [b,h,s,d]
// MODE 2: plain projection -> [b,h,s,d]
// MODE 3: A from [b,h,s,d] ctx; out = A@W + residual
// ---------------------------------------------------------------------------
template<int MODE>
__global__ void __launch_bounds__(256, 2) gemm128_k(
    const float* __restrict__ A, const float* __restrict__ Bw,
    const float* __restrict__ aux, float* __restrict__ C)
{
    __shared__ float As[16][132];
    __shared__ float Bs[16][132];
    const int tid = threadIdx.x;
    const int m0 = blockIdx.y * 128, n0 = blockIdx.x * 128;
    const int ty = tid >> 4, tx = tid & 15;

    u64 acc[8][4] = {};

    for (int k0 = 0; k0 < DMODEL; k0 += 16) {
        // A tile: 128 rows x 16 k, stored transposed As[k][m]
        #pragma unroll
        for (int i = 0; i < 2; i++) {
            int idx = tid + i * 256;
            int row = idx >> 2, kq = idx & 3;
            float4 a4;
            if (MODE == 3) {
                int m = m0 + row;
                int b = m >> 11, s = m & (SEQ - 1);
                int kk = k0 + kq * 4;
                int h = kk >> 6, d = kk & 63;
                a4 = *(const float4*)&A[(((size_t)(b * NH + h)) * SEQ + s) * DH + d];
            } else {
                a4 = *(const float4*)&A[(size_t)(m0 + row) * DMODEL + k0 + kq * 4];
            }
            As[kq * 4 + 0][row] = a4.x; As[kq * 4 + 1][row] = a4.y;
            As[kq * 4 + 2][row] = a4.z; As[kq * 4 + 3][row] = a4.w;
        }
        // B tile: 16 k x 128 n, direct
        #pragma unroll
        for (int i = 0; i < 2; i++) {
            int idx = tid + i * 256;
            int kk = idx >> 5, nq = idx & 31;
            *(float4*)&Bs[kk][nq * 4] =
                *(const float4*)&Bw[(size_t)(k0 + kk) * DMODEL + n0 + nq * 4];
        }
        __syncthreads();

        #pragma unroll
        for (int k = 0; k < 16; k++)
            FMA8x8(As[k], Bs[k], ty * 4, 64 + ty * 4, tx * 4, 64 + tx * 4, acc);
        __syncthreads();
    }

    // Epilogue: rows {ty*4+i, 64+ty*4+i}, col groups {tx*4, 64+tx*4}
    #pragma unroll
    for (int i = 0; i < 8; i++) {
        int m = m0 + ((i < 4) ? ty * 4 + i : 64 + ty * 4 + (i - 4));
        #pragma unroll
        for (int jg = 0; jg < 2; jg++) {
            int n = n0 + jg * 64 + tx * 4;
            float4 v = up4(acc[i][jg * 2], acc[i][jg * 2 + 1]);
            if (MODE == 0) {
                float4 bb = *(const float4*)&aux[n];
                v.x = 1.0f + 1.0f / (1.0f + __expf(-(v.x + bb.x)));
                v.y = 1.0f + 1.0f / (1.0f + __expf(-(v.y + bb.y)));
                v.z = 1.0f + 1.0f / (1.0f + __expf(-(v.z + bb.z)));
                v.w = 1.0f + 1.0f / (1.0f + __expf(-(v.w + bb.w)));
                *(float4*)&C[(size_t)m * DMODEL + n] = v;
            } else if (MODE == 1 || MODE == 2) {
                if (MODE == 1) {
                    float4 cf = *(const float4*)&aux[(size_t)m * DMODEL + n];
                    v.x *= cf.x; v.y *= cf.y; v.z *= cf.z; v.w *= cf.w;
                }
                int b = m >> 11, s = m & (SEQ - 1);
                int h = n >> 6, d = n & 63;   // 4 consecutive d within one head
                *(float4*)&C[(((size_t)(b * NH + h)) * SEQ + s) * DH + d] = v;
            } else { // MODE 3
                float4 r = *(const float4*)&aux[(size_t)m * DMODEL + n];
                v.x += r.x; v.y += r.y; v.z += r.z; v.w += r.w;
                *(float4*)&C[(size_t)m * DMODEL + n] = v;
            }
        }
    }
}

// ---------------------------------------------------------------------------
// Pass 1: P = exp(mask ? -inf : dist * (Q.K)/8) unnormalized, + rowsums.
// Block: 128 s-rows x full 2048 t; 128x128 score tiles, d chunked by 16.
// ---------------------------------------------------------------------------
__global__ void __launch_bounds__(256, 2) attn_scores_k(
    const float* __restrict__ Q, const float* __restrict__ Kx,
    const float* __restrict__ dist, const void* __restrict__ mask,
    float* __restrict__ P, float* __restrict__ rowsum)
{
    __shared__ float Qs[16][132];
    __shared__ float Ks[16][132];
    const int tid = threadIdx.x;
    const int h = blockIdx.x, st = blockIdx.y, b = blockIdx.z;
    const int bh = b * NH + h;
    const int s0 = st * 128;
    const int kind = g_mask_kind;
    const int ty = tid >> 4, tx = tid & 15;

    float rowacc[8] = {};

    const unsigned char* m8 = (const unsigned char*)mask;
    const int*           mi = (const int*)mask;
    const float*         mf = (const float*)mask;

    for (int t0 = 0; t0 < SEQ; t0 += 128) {
        u64 acc[8][4] = {};

        for (int dc = 0; dc < DH; dc += 16) {
            #pragma unroll
            for (int i = 0; i < 2; i++) {
                int idx = tid + i * 256;
                int row = idx >> 2, kq = idx & 3;
                float4 q4 = *(const float4*)&Q[((size_t)bh * SEQ + s0 + row) * DH + dc + kq * 4];
                Qs[kq * 4 + 0][row] = q4.x; Qs[kq * 4 + 1][row] = q4.y;
                Qs[kq * 4 + 2][row] = q4.z; Qs[kq * 4 + 3][row] = q4.w;
                float4 k4 = *(const float4*)&Kx[((size_t)bh * SEQ + t0 + row) * DH + dc + kq * 4];
                Ks[kq * 4 + 0][row] = k4.x; Ks[kq * 4 + 1][row] = k4.y;
                Ks[kq * 4 + 2][row] = k4.z; Ks[kq * 4 + 3][row] = k4.w;
            }
            __syncthreads();
            #pragma unroll
            for (int k = 0; k < 16; k++)
                FMA8x8(Qs[k], Ks[k], ty * 4, 64 + ty * 4, tx * 4, 64 + tx * 4, acc);
            __syncthreads();
        }

        #pragma unroll
        for (int i = 0; i < 8; i++) {
            int s = s0 + ((i < 4) ? ty * 4 + i : 64 + ty * 4 + (i - 4));
            size_t drow = ((size_t)b * SEQ + s) * SEQ;
            size_t prow = ((size_t)bh * SEQ + s) * SEQ;
            #pragma unroll
            for (int jg = 0; jg < 2; jg++) {
                int t = t0 + jg * 64 + tx * 4;
                float4 sc = up4(acc[i][jg * 2], acc[i][jg * 2 + 1]);
                float4 d4 = *(const float4*)&dist[drow + t];
                sc.x *= 0.125f * d4.x; sc.y *= 0.125f * d4.y;
                sc.z *= 0.125f * d4.z; sc.w *= 0.125f * d4.w;
                bool k0b, k1b, k2b, k3b;
                if (kind == 0) {
                    uchar4 mc = *(const uchar4*)&m8[drow + t];
                    k0b = mc.x; k1b = mc.y; k2b = mc.z; k3b = mc.w;
                } else if (kind == 1) {
                    int4 mc = *(const int4*)&mi[drow + t];
                    k0b = mc.x; k1b = mc.y; k2b = mc.z; k3b = mc.w;
                } else {
                    float4 mc = *(const float4*)&mf[drow + t];
                    k0b = mc.x != 0.0f; k1b = mc.y != 0.0f;
                    k2b = mc.z != 0.0f; k3b = mc.w != 0.0f;
                }
                float4 p;
                p.x = k0b ? 0.0f : __expf(sc.x);
                p.y = k1b ? 0.0f : __expf(sc.y);
                p.z = k2b ? 0.0f : __expf(sc.z);
                p.w = k3b ? 0.0f : __expf(sc.w);
                *(float4*)&P[prow + t] = p;
                rowacc[i] += p.x + p.y + p.z + p.w;
            }
        }
    }

    #pragma unroll
    for (int i = 0; i < 8; i++) {
        float v = rowacc[i];
        v += __shfl_xor_sync(0xffffffffu, v, 1);
        v += __shfl_xor_sync(0xffffffffu, v, 2);
        v += __shfl_xor_sync(0xffffffffu, v, 4);
        v += __shfl_xor_sync(0xffffffffu, v, 8);
        if (tx == 0) {
            int s = s0 + ((i < 4) ? ty * 4 + i : 64 + ty * 4 + (i - 4));
            rowsum[(size_t)bh * SEQ + s] = v;
        }
    }
}

// ---------------------------------------------------------------------------
// Pass 2: normalize P (optional writeback) and ctx = Pn @ V.
// Block: 256 s-rows x 64 d, t chunked by 16; 8x8 tiles (FFMA2).
// ---------------------------------------------------------------------------
__global__ void __launch_bounds__(256, 2) attn_pv_k(
    float* __restrict__ P, const float* __restrict__ V,
    const float* __restrict__ rowsum, float* __restrict__ ctx, int writeback)
{
    __shared__ float Ps[16][260];   // [t][s]
    __shared__ float Vs[16][68];    // [t][d]
    __shared__ float invs[256];
    const int tid = threadIdx.x;
    const int h = blockIdx.x, st = blockIdx.y, b = blockIdx.z;
    const int bh = b * NH + h;
    const int s0 = st * 256;
    const int ty = tid >> 3, tx = tid & 7;

    invs[tid] = 1.0f / rowsum[(size_t)bh * SEQ + s0 + tid];
    __syncthreads();

    u64 acc[8][4] = {};

    for (int t0 = 0; t0 < SEQ; t0 += 16) {
        // P chunk: 256 s x 16 t, normalize on load, transpose to Ps[t][s]
        #pragma unroll
        for (int i = 0; i < 4; i++) {
            int idx = tid + i * 256;
            int row = idx >> 2, tq = idx & 3;
            size_t off = ((size_t)bh * SEQ + s0 + row) * SEQ + t0 + tq * 4;
            float4 p4 = *(const float4*)&P[off];
            float inv = invs[row];
            p4.x *= inv; p4.y *= inv; p4.z *= inv; p4.w *= inv;
            if (writeback) *(float4*)&P[off] = p4;
            Ps[tq * 4 + 0][row] = p4.x; Ps[tq * 4 + 1][row] = p4.y;
            Ps[tq * 4 + 2][row] = p4.z; Ps[tq * 4 + 3][row] = p4.w;
        }
        // V chunk: 16 t x 64 d
        {
            int kk = tid >> 4, dq = tid & 15;
            *(float4*)&Vs[kk][dq * 4] =
                *(const float4*)&V[((size_t)bh * SEQ + t0 + kk) * DH + dq * 4];
        }
        __syncthreads();

        #pragma unroll
        for (int k = 0; k < 16; k++)
            FMA8x8(Ps[k], Vs[k], ty * 4, 128 + ty * 4, tx * 4, 32 + tx * 4, acc);
        __syncthreads();
    }

    #pragma unroll
    for (int i = 0; i < 8; i++) {
        int s = s0 + ((i < 4) ? ty * 4 + i : 128 + ty * 4 + (i - 4));
        #pragma unroll
        for (int jg = 0; jg < 2; jg++) {
            int d = jg * 32 + tx * 4;
            float4 v = up4(acc[i][jg * 2], acc[i][jg * 2 + 1]);
            *(float4*)&ctx[((size_t)bh * SEQ + s) * DH + d] = v;
        }
    }
}

// ---------------------------------------------------------------------------
// Launch
// ---------------------------------------------------------------------------
extern "C" void kernel_launch(void* const* d_in, const int* in_sizes, int n_in,
                              void* d_out, int out_size)
{
    const float* inQ   = (const float*)d_in[0];
    const float* inK   = (const float*)d_in[1];
    const float* inV   = (const float*)d_in[2];
    const float* inter = (const float*)d_in[3];
    const float* dist  = (const float*)d_in[4];
    const void*  mask  = d_in[5];
    const float* W_Q   = (const float*)d_in[6];
    const float* W_K   = (const float*)d_in[7];
    const float* W_V   = (const float*)d_in[8];
    const float* W_fc  = (const float*)d_in[9];
    const float* We_w  = (const float*)d_in[10];
    const float* We_b  = (const float*)d_in[11];
    float* out = (float*)d_out;

    void *coefp_, *qp_, *kp_, *vp_, *ctxp_, *rsp_, *pbuf_;
    cudaGetSymbolAddress(&coefp_, g_coef);
    cudaGetSymbolAddress(&qp_,    g_Qb);
    cudaGetSymbolAddress(&kp_,    g_Kb);
    cudaGetSymbolAddress(&vp_,    g_Vb);
    cudaGetSymbolAddress(&ctxp_,  g_ctx);
    cudaGetSymbolAddress(&rsp_,   g_rowsum);
    cudaGetSymbolAddress(&pbuf_,  g_Pbuf);
    float* coefp = (float*)coefp_;
    float* Qp    = (float*)qp_;
    float* Kp    = (float*)kp_;
    float* Vp    = (float*)vp_;
    float* ctxp  = (float*)ctxp_;
    float* rsp   = (float*)rsp_;

    const bool need_attn = ((size_t)out_size >= OUT_ELEMS + ATTN_ELEMS);
    float* P = need_attn ? (out + OUT_ELEMS) : (float*)pbuf_;

    dim3 thr(256);
    dim3 gemm_grid(DMODEL / 128, MTOT / 128);     // (8, 32)
    dim3 sc_grid(NH, SEQ / 128, BB);              // (16, 16, 2)
    dim3 pv_grid(NH, SEQ / 256, BB);              // (16, 8, 2)

    detect_mask_kind_k<<<1, 256>>>((const unsigned char*)mask);

    gemm128_k<0><<<gemm_grid, thr>>>(inter, We_w, We_b, coefp);
    gemm128_k<1><<<gemm_grid, thr>>>(inQ,   W_Q,  coefp, Qp);
    gemm128_k<1><<<gemm_grid, thr>>>(inK,   W_K,  coefp, Kp);
    gemm128_k<2><<<gemm_grid, thr>>>(inV,   W_V,  nullptr, Vp);

    attn_scores_k<<<sc_grid, thr>>>(Qp, Kp, dist, mask, P, rsp);
    attn_pv_k<<<pv_grid, thr>>>(P, Vp, rsp, ctxp, need_attn ? 1 : 0);

    gemm128_k<3><<<gemm_grid, thr>>>(ctxp, W_fc, inQ, out);
}

// round 15
// speedup vs baseline: 1.1783x; 1.1545x over previous
#include <cuda_runtime.h>
#include <cuda_bf16.h>
#include <math.h>
#include <stdint.h>

// Problem constants
#define BB   2
#define SEQ  2048
#define DMODEL 1024
#define NH   16
#define DH   64
#define BH   (BB*NH)          // 32
#define MTOT (BB*SEQ)         // 4096

#define OUT_ELEMS  ((size_t)MTOT * DMODEL)          // 4,194,304
#define ATTN_ELEMS ((size_t)BH * SEQ * SEQ)         // 134,217,728

typedef unsigned long long u64;

// ===========================================================================
// HMMA m16n8k16 bf16 (portable PTX, works on compute_103 virtual arch)
// ===========================================================================
__device__ __forceinline__ void mma_bf16(float* c, const uint32_t* a, const uint32_t* b) {
    asm volatile(
        "mma.sync.aligned.m16n8k16.row.col.f32.bf16.bf16.f32 "
        "{%0,%1,%2,%3}, {%4,%5,%6,%7}, {%8,%9}, {%0,%1,%2,%3};"
        : "+f"(c[0]), "+f"(c[1]), "+f"(c[2]), "+f"(c[3])
        : "r"(a[0]), "r"(a[1]), "r"(a[2]), "r"(a[3]), "r"(b[0]), "r"(b[1]));
}

// bf16 split/pack helpers
__device__ __forceinline__ uint32_t pack_hi2(float a, float b, float& ra, float& rb) {
    __nv_bfloat16 ha = __float2bfloat16(a), hb = __float2bfloat16(b);
    ra = a - __bfloat162float(ha); rb = b - __bfloat162float(hb);
    __nv_bfloat162 p = __halves2bfloat162(ha, hb);
    return *reinterpret_cast<uint32_t*>(&p);
}
__device__ __forceinline__ uint32_t pack_bf2(float a, float b) {
    __nv_bfloat162 p = __floats2bfloat162_rn(a, b);
    return *reinterpret_cast<uint32_t*>(&p);
}

// ===========================================================================
// Packed fp32x2 FMA helpers (for the attention kernels)
// ===========================================================================
__device__ __forceinline__ u64 pk2(float lo, float hi) {
    u64 r; asm("mov.b64 %0, {%1, %2};" : "=l"(r) : "f"(lo), "f"(hi)); return r;
}
__device__ __forceinline__ u64 dup2(float v) {
    u64 r; asm("mov.b64 %0, {%1, %1};" : "=l"(r) : "f"(v)); return r;
}
__device__ __forceinline__ void fma2(u64& d, u64 a, u64 b) {
    asm("fma.rn.f32x2 %0, %1, %2, %0;" : "+l"(d) : "l"(a), "l"(b));
}
__device__ __forceinline__ float2 up2(u64 v) {
    float2 r; asm("mov.b64 {%0, %1}, %2;" : "=f"(r.x), "=f"(r.y) : "l"(v)); return r;
}
__device__ __forceinline__ float4 up4(u64 p0, u64 p1) {
    float2 a = up2(p0), b = up2(p1);
    return make_float4(a.x, a.y, b.x, b.y);
}
#define FMA8x8(ASP, BSP, OA0, OA1, OB0, OB1, ACC) do {                        \
    float4 _aA = *(const float4*)&(ASP)[(OA0)];                               \
    float4 _aB = *(const float4*)&(ASP)[(OA1)];                               \
    float4 _bA = *(const float4*)&(BSP)[(OB0)];                               \
    float4 _bB = *(const float4*)&(BSP)[(OB1)];                               \
    u64 _b0 = pk2(_bA.x,_bA.y), _b1 = pk2(_bA.z,_bA.w);                       \
    u64 _b2 = pk2(_bB.x,_bB.y), _b3 = pk2(_bB.z,_bB.w);                       \
    float _av[8] = {_aA.x,_aA.y,_aA.z,_aA.w,_aB.x,_aB.y,_aB.z,_aB.w};         \
    _Pragma("unroll")                                                         \
    for (int _i = 0; _i < 8; _i++) {                                          \
        u64 _ai = dup2(_av[_i]);                                              \
        fma2((ACC)[_i][0], _ai, _b0); fma2((ACC)[_i][1], _ai, _b1);           \
        fma2((ACC)[_i][2], _ai, _b2); fma2((ACC)[_i][3], _ai, _b3);           \
    }                                                                         \
} while (0)

// ===========================================================================
// Scratch
// ===========================================================================
__device__ float g_coef[MTOT * DMODEL];
__device__ float g_Qb[BH * SEQ * DH];
__device__ float g_Kb[BH * SEQ * DH];
__device__ float g_Vb[BH * SEQ * DH];
__device__ float g_ctx[BH * SEQ * DH];
__device__ float g_rowsum[BH * SEQ];
__device__ float g_Pbuf[ATTN_ELEMS];
__device__ int   g_mask_kind;   // 0=u8, 1=i32, 2=f32
// bf16 split transposed weights [N,K], 5 weights: We_w, W_Q, W_K, W_V, W_fc
__device__ __nv_bfloat16 g_Whi[5 * DMODEL * DMODEL];
__device__ __nv_bfloat16 g_Wlo[5 * DMODEL * DMODEL];

// ===========================================================================
// Mask dtype detector
// ===========================================================================
__global__ void detect_mask_kind_k(const unsigned char* __restrict__ m) {
    __shared__ int odd1, f3;
    if (threadIdx.x == 0) { odd1 = 0; f3 = 0; }
    __syncthreads();
    int lo = 0, lf = 0;
    for (int i = threadIdx.x; i < 4096; i += blockDim.x) {
        unsigned char b = m[i];
        if ((i & 3) != 0 && b == 1)    lo = 1;
        if ((i & 3) == 3 && b == 0x3F) lf = 1;
    }
    if (lo) atomicOr(&odd1, 1);
    if (lf) atomicOr(&f3, 1);
    __syncthreads();
    if (threadIdx.x == 0) g_mask_kind = odd1 ? 0 : (f3 ? 2 : 1);
}

// ===========================================================================
// Weight prep: transpose fp32 W [K,N] -> bf16 hi/lo [N,K]
// ===========================================================================
__global__ void __launch_bounds__(256) wconv_k(
    const float* __restrict__ W,
    __nv_bfloat16* __restrict__ hiT, __nv_bfloat16* __restrict__ loT)
{
    __shared__ float t[32][33];
    const int n0 = blockIdx.x * 32, k0 = blockIdx.y * 32;
    const int tx = threadIdx.x & 31, ty = threadIdx.x >> 5;
    #pragma unroll
    for (int i = 0; i < 4; i++) {
        int kk = ty + i * 8;
        t[kk][tx] = W[(size_t)(k0 + kk) * DMODEL + n0 + tx];
    }
    __syncthreads();
    #pragma unroll
    for (int i = 0; i < 4; i++) {
        int nn = ty + i * 8;
        float x = t[tx][nn];                 // W[k0+tx][n0+nn]
        __nv_bfloat16 h = __float2bfloat16(x);
        float r = x - __bfloat162float(h);
        size_t o = (size_t)(n0 + nn) * DMODEL + k0 + tx;
        hiT[o] = h;
        loT[o] = __float2bfloat16(r);
    }
}

// ===========================================================================
// HMMA bf16-split GEMM: 128x128 per CTA, 256 thr, 8 warps (2m x 4n),
// warp tile 64x32, K chunked by 64.  D = Ahi*Bhi + Ahi*Blo + Alo*Bhi.
// smem: 4 arrays [128 rows][72 bf16] (row stride 36 b32 -> conflict-free
// frag LDS.32: bank = (4*row + kb32) mod 32).
// MODE 0: coef = 1 + sigmoid(A@W + bias)
// MODE 1: (A@W) * coef -> [b,h,s,d]
// MODE 2: plain -> [b,h,s,d]
// MODE 3: A from [b,h,s,d]; C = A@W + residual
// ===========================================================================
#define SMB_STRIDE 36                       // b32 per row
#define SM_ARR (128 * SMB_STRIDE)           // u32 elements per array
#define SM_TOTAL (4 * SM_ARR * 4)           // 73728 bytes

template<int MODE>
__global__ void __launch_bounds__(256) gemm_hmma_k(
    const float* __restrict__ A,
    const __nv_bfloat16* __restrict__ BhiT, const __nv_bfloat16* __restrict__ BloT,
    const float* __restrict__ aux, float* __restrict__ C)
{
    extern __shared__ uint32_t sm[];
    uint32_t* sAhi = sm;
    uint32_t* sAlo = sAhi + SM_ARR;
    uint32_t* sBhi = sAlo + SM_ARR;
    uint32_t* sBlo = sBhi + SM_ARR;

    const int tid = threadIdx.x;
    const int m0 = blockIdx.y * 128, n0 = blockIdx.x * 128;
    const int wid = tid >> 5, lane = tid & 31;
    const int wm = (wid & 1) * 64, wn = (wid >> 1) * 32;
    const int g = lane >> 2, cc = lane & 3;

    const int row  = tid >> 1;           // 0..127
    const int kseg = (tid & 1) * 32;     // bf16 offset within 64-chunk

    float acc[4][4][4] = {};             // [mt][nt][c0..c3]

    for (int ch = 0; ch < 16; ch++) {
        const int k0 = ch * 64;

        // ---- global loads (issue before sync; overlap with prior compute) ----
        float4 a[8];
        if (MODE == 3) {
            int m = m0 + row;
            int b = m >> 11, s = m & (SEQ - 1);
            int h = k0 >> 6;             // 64-chunk == one head
            const float* src = &A[(((size_t)(b * NH + h)) * SEQ + s) * DH + kseg];
            #pragma unroll
            for (int q = 0; q < 8; q++) a[q] = *(const float4*)&src[q * 4];
        } else {
            const float* src = &A[(size_t)(m0 + row) * DMODEL + k0 + kseg];
            #pragma unroll
            for (int q = 0; q < 8; q++) a[q] = *(const float4*)&src[q * 4];
        }
        uint4 bh4[4], bl4[4];
        {
            const size_t bo = (size_t)(n0 + row) * DMODEL + k0 + kseg;
            #pragma unroll
            for (int q = 0; q < 4; q++) {
                bh4[q] = *(const uint4*)&BhiT[bo + q * 8];
                bl4[q] = *(const uint4*)&BloT[bo + q * 8];
            }
        }

        __syncthreads();   // consumers of previous chunk done with smem

        // ---- convert + store ----
        #pragma unroll
        for (int q = 0; q < 4; q++) {
            float4 f0 = a[q * 2], f1 = a[q * 2 + 1];
            float r0, r1, r2, r3, r4, r5, r6, r7;
            uint4 hi4, lo4;
            hi4.x = pack_hi2(f0.x, f0.y, r0, r1);
            hi4.y = pack_hi2(f0.z, f0.w, r2, r3);
            hi4.z = pack_hi2(f1.x, f1.y, r4, r5);
            hi4.w = pack_hi2(f1.z, f1.w, r6, r7);
            lo4.x = pack_bf2(r0, r1); lo4.y = pack_bf2(r2, r3);
            lo4.z = pack_bf2(r4, r5); lo4.w = pack_bf2(r6, r7);
            int off = row * SMB_STRIDE + (kseg >> 1) + q * 4;
            *(uint4*)&sAhi[off] = hi4;
            *(uint4*)&sAlo[off] = lo4;
            *(uint4*)&sBhi[off] = bh4[q];
            *(uint4*)&sBlo[off] = bl4[q];
        }
        __syncthreads();

        // ---- consume: 4 x k16 ----
        #pragma unroll
        for (int kc = 0; kc < 4; kc++) {
            uint32_t ah[4][4], al[4][4];
            #pragma unroll
            for (int mt = 0; mt < 4; mt++) {
                int i0 = (wm + mt * 16 + g) * SMB_STRIDE + kc * 8 + cc;
                int i1 = i0 + 8 * SMB_STRIDE;
                ah[mt][0] = sAhi[i0];     ah[mt][1] = sAhi[i1];
                ah[mt][2] = sAhi[i0 + 4]; ah[mt][3] = sAhi[i1 + 4];
                al[mt][0] = sAlo[i0];     al[mt][1] = sAlo[i1];
                al[mt][2] = sAlo[i0 + 4]; al[mt][3] = sAlo[i1 + 4];
            }
            #pragma unroll
            for (int nt = 0; nt < 4; nt++) {
                int bi = (wn + nt * 8 + g) * SMB_STRIDE + kc * 8 + cc;
                uint32_t bh[2] = { sBhi[bi], sBhi[bi + 4] };
                uint32_t bl[2] = { sBlo[bi], sBlo[bi + 4] };
                #pragma unroll
                for (int mt = 0; mt < 4; mt++) {
                    mma_bf16(acc[mt][nt], ah[mt], bh);
                    mma_bf16(acc[mt][nt], ah[mt], bl);
                    mma_bf16(acc[mt][nt], al[mt], bh);
                }
            }
        }
    }

    // ---- epilogue: c0,c1 -> (m, n..n+1); c2,c3 -> (m+8, n..n+1) ----
    auto epi = [&](int m, int n, float2 v) {
        if (MODE == 0) {
            float2 bb = *(const float2*)&aux[n];
            v.x = 1.0f + 1.0f / (1.0f + __expf(-(v.x + bb.x)));
            v.y = 1.0f + 1.0f / (1.0f + __expf(-(v.y + bb.y)));
            *(float2*)&C[(size_t)m * DMODEL + n] = v;
        } else if (MODE == 1 || MODE == 2) {
            if (MODE == 1) {
                float2 cf = *(const float2*)&aux[(size_t)m * DMODEL + n];
                v.x *= cf.x; v.y *= cf.y;
            }
            int b = m >> 11, s = m & (SEQ - 1);
            int h = n >> 6, d = n & 63;
            *(float2*)&C[(((size_t)(b * NH + h)) * SEQ + s) * DH + d] = v;
        } else {
            float2 r = *(const float2*)&aux[(size_t)m * DMODEL + n];
            v.x += r.x; v.y += r.y;
            *(float2*)&C[(size_t)m * DMODEL + n] = v;
        }
    };

    #pragma unroll
    for (int mt = 0; mt < 4; mt++) {
        #pragma unroll
        for (int nt = 0; nt < 4; nt++) {
            int m = m0 + wm + mt * 16 + g;
            int n = n0 + wn + nt * 8 + 2 * cc;
            epi(m,     n, make_float2(acc[mt][nt][0], acc[mt][nt][1]));
            epi(m + 8, n, make_float2(acc[mt][nt][2], acc[mt][nt][3]));
        }
    }
}

// ===========================================================================
// Pass 1: P = exp(mask ? -inf : dist * (Q.K)/8) unnormalized, + rowsums.
// ===========================================================================
__global__ void __launch_bounds__(256, 2) attn_scores_k(
    const float* __restrict__ Q, const float* __restrict__ Kx,
    const float* __restrict__ dist, const void* __restrict__ mask,
    float* __restrict__ P, float* __restrict__ rowsum)
{
    __shared__ float Qs[16][132];
    __shared__ float Ks[16][132];
    const int tid = threadIdx.x;
    const int h = blockIdx.x, st = blockIdx.y, b = blockIdx.z;
    const int bh = b * NH + h;
    const int s0 = st * 128;
    const int kind = g_mask_kind;
    const int ty = tid >> 4, tx = tid & 15;

    float rowacc[8] = {};

    const unsigned char* m8 = (const unsigned char*)mask;
    const int*           mi = (const int*)mask;
    const float*         mf = (const float*)mask;

    for (int t0 = 0; t0 < SEQ; t0 += 128) {
        u64 acc[8][4] = {};

        for (int dc = 0; dc < DH; dc += 16) {
            #pragma unroll
            for (int i = 0; i < 2; i++) {
                int idx = tid + i * 256;
                int row = idx >> 2, kq = idx & 3;
                float4 q4 = *(const float4*)&Q[((size_t)bh * SEQ + s0 + row) * DH + dc + kq * 4];
                Qs[kq * 4 + 0][row] = q4.x; Qs[kq * 4 + 1][row] = q4.y;
                Qs[kq * 4 + 2][row] = q4.z; Qs[kq * 4 + 3][row] = q4.w;
                float4 k4 = *(const float4*)&Kx[((size_t)bh * SEQ + t0 + row) * DH + dc + kq * 4];
                Ks[kq * 4 + 0][row] = k4.x; Ks[kq * 4 + 1][row] = k4.y;
                Ks[kq * 4 + 2][row] = k4.z; Ks[kq * 4 + 3][row] = k4.w;
            }
            __syncthreads();
            #pragma unroll
            for (int k = 0; k < 16; k++)
                FMA8x8(Qs[k], Ks[k], ty * 4, 64 + ty * 4, tx * 4, 64 + tx * 4, acc);
            __syncthreads();
        }

        #pragma unroll
        for (int i = 0; i < 8; i++) {
            int s = s0 + ((i < 4) ? ty * 4 + i : 64 + ty * 4 + (i - 4));
            size_t drow = ((size_t)b * SEQ + s) * SEQ;
            size_t prow = ((size_t)bh * SEQ + s) * SEQ;
            #pragma unroll
            for (int jg = 0; jg < 2; jg++) {
                int t = t0 + jg * 64 + tx * 4;
                float4 sc = up4(acc[i][jg * 2], acc[i][jg * 2 + 1]);
                float4 d4 = *(const float4*)&dist[drow + t];
                sc.x *= 0.125f * d4.x; sc.y *= 0.125f * d4.y;
                sc.z *= 0.125f * d4.z; sc.w *= 0.125f * d4.w;
                bool k0b, k1b, k2b, k3b;
                if (kind == 0) {
                    uchar4 mc = *(const uchar4*)&m8[drow + t];
                    k0b = mc.x; k1b = mc.y; k2b = mc.z; k3b = mc.w;
                } else if (kind == 1) {
                    int4 mc = *(const int4*)&mi[drow + t];
                    k0b = mc.x; k1b = mc.y; k2b = mc.z; k3b = mc.w;
                } else {
                    float4 mc = *(const float4*)&mf[drow + t];
                    k0b = mc.x != 0.0f; k1b = mc.y != 0.0f;
                    k2b = mc.z != 0.0f; k3b = mc.w != 0.0f;
                }
                float4 p;
                p.x = k0b ? 0.0f : __expf(sc.x);
                p.y = k1b ? 0.0f : __expf(sc.y);
                p.z = k2b ? 0.0f : __expf(sc.z);
                p.w = k3b ? 0.0f : __expf(sc.w);
                *(float4*)&P[prow + t] = p;
                rowacc[i] += p.x + p.y + p.z + p.w;
            }
        }
    }

    #pragma unroll
    for (int i = 0; i < 8; i++) {
        float v = rowacc[i];
        v += __shfl_xor_sync(0xffffffffu, v, 1);
        v += __shfl_xor_sync(0xffffffffu, v, 2);
        v += __shfl_xor_sync(0xffffffffu, v, 4);
        v += __shfl_xor_sync(0xffffffffu, v, 8);
        if (tx == 0) {
            int s = s0 + ((i < 4) ? ty * 4 + i : 64 + ty * 4 + (i - 4));
            rowsum[(size_t)bh * SEQ + s] = v;
        }
    }
}

// ===========================================================================
// Pass 2: normalize P (optional writeback) and ctx = Pn @ V.
// ===========================================================================
__global__ void __launch_bounds__(256, 2) attn_pv_k(
    float* __restrict__ P, const float* __restrict__ V,
    const float* __restrict__ rowsum, float* __restrict__ ctx, int writeback)
{
    __shared__ float Ps[16][260];
    __shared__ float Vs[16][68];
    __shared__ float invs[256];
    const int tid = threadIdx.x;
    const int h = blockIdx.x, st = blockIdx.y, b = blockIdx.z;
    const int bh = b * NH + h;
    const int s0 = st * 256;
    const int ty = tid >> 3, tx = tid & 7;

    invs[tid] = 1.0f / rowsum[(size_t)bh * SEQ + s0 + tid];
    __syncthreads();

    u64 acc[8][4] = {};

    for (int t0 = 0; t0 < SEQ; t0 += 16) {
        #pragma unroll
        for (int i = 0; i < 4; i++) {
            int idx = tid + i * 256;
            int row = idx >> 2, tq = idx & 3;
            size_t off = ((size_t)bh * SEQ + s0 + row) * SEQ + t0 + tq * 4;
            float4 p4 = *(const float4*)&P[off];
            float inv = invs[row];
            p4.x *= inv; p4.y *= inv; p4.z *= inv; p4.w *= inv;
            if (writeback) *(float4*)&P[off] = p4;
            Ps[tq * 4 + 0][row] = p4.x; Ps[tq * 4 + 1][row] = p4.y;
            Ps[tq * 4 + 2][row] = p4.z; Ps[tq * 4 + 3][row] = p4.w;
        }
        {
            int kk = tid >> 4, dq = tid & 15;
            *(float4*)&Vs[kk][dq * 4] =
                *(const float4*)&V[((size_t)bh * SEQ + t0 + kk) * DH + dq * 4];
        }
        __syncthreads();

        #pragma unroll
        for (int k = 0; k < 16; k++)
            FMA8x8(Ps[k], Vs[k], ty * 4, 128 + ty * 4, tx * 4, 32 + tx * 4, acc);
        __syncthreads();
    }

    #pragma unroll
    for (int i = 0; i < 8; i++) {
        int s = s0 + ((i < 4) ? ty * 4 + i : 128 + ty * 4 + (i - 4));
        #pragma unroll
        for (int jg = 0; jg < 2; jg++) {
            int d = jg * 32 + tx * 4;
            float4 v = up4(acc[i][jg * 2], acc[i][jg * 2 + 1]);
            *(float4*)&ctx[((size_t)bh * SEQ + s) * DH + d] = v;
        }
    }
}

// ===========================================================================
// Launch
// ===========================================================================
extern "C" void kernel_launch(void* const* d_in, const int* in_sizes, int n_in,
                              void* d_out, int out_size)
{
    const float* inQ   = (const float*)d_in[0];
    const float* inK   = (const float*)d_in[1];
    const float* inV   = (const float*)d_in[2];
    const float* inter = (const float*)d_in[3];
    const float* dist  = (const float*)d_in[4];
    const void*  mask  = d_in[5];
    const float* W_Q   = (const float*)d_in[6];
    const float* W_K   = (const float*)d_in[7];
    const float* W_V   = (const float*)d_in[8];
    const float* W_fc  = (const float*)d_in[9];
    const float* We_w  = (const float*)d_in[10];
    const float* We_b  = (const float*)d_in[11];
    float* out = (float*)d_out;

    void *coefp_, *qp_, *kp_, *vp_, *ctxp_, *rsp_, *pbuf_, *whi_, *wlo_;
    cudaGetSymbolAddress(&coefp_, g_coef);
    cudaGetSymbolAddress(&qp_,    g_Qb);
    cudaGetSymbolAddress(&kp_,    g_Kb);
    cudaGetSymbolAddress(&vp_,    g_Vb);
    cudaGetSymbolAddress(&ctxp_,  g_ctx);
    cudaGetSymbolAddress(&rsp_,   g_rowsum);
    cudaGetSymbolAddress(&pbuf_,  g_Pbuf);
    cudaGetSymbolAddress(&whi_,   g_Whi);
    cudaGetSymbolAddress(&wlo_,   g_Wlo);
    float* coefp = (float*)coefp_;
    float* Qp    = (float*)qp_;
    float* Kp    = (float*)kp_;
    float* Vp    = (float*)vp_;
    float* ctxp  = (float*)ctxp_;
    float* rsp   = (float*)rsp_;
    __nv_bfloat16* Whi = (__nv_bfloat16*)whi_;
    __nv_bfloat16* Wlo = (__nv_bfloat16*)wlo_;
    const size_t WSZ = (size_t)DMODEL * DMODEL;

    const bool need_attn = ((size_t)out_size >= OUT_ELEMS + ATTN_ELEMS);
    float* P = need_attn ? (out + OUT_ELEMS) : (float*)pbuf_;

    cudaFuncSetAttribute(gemm_hmma_k<0>, cudaFuncAttributeMaxDynamicSharedMemorySize, SM_TOTAL);
    cudaFuncSetAttribute(gemm_hmma_k<1>, cudaFuncAttributeMaxDynamicSharedMemorySize, SM_TOTAL);
    cudaFuncSetAttribute(gemm_hmma_k<2>, cudaFuncAttributeMaxDynamicSharedMemorySize, SM_TOTAL);
    cudaFuncSetAttribute(gemm_hmma_k<3>, cudaFuncAttributeMaxDynamicSharedMemorySize, SM_TOTAL);

    dim3 thr(256);
    dim3 wgrid(DMODEL / 32, DMODEL / 32);        // (32, 32)
    dim3 ggrid(DMODEL / 128, MTOT / 128);        // (8, 32)
    dim3 sc_grid(NH, SEQ / 128, BB);
    dim3 pv_grid(NH, SEQ / 256, BB);

    detect_mask_kind_k<<<1, 256>>>((const unsigned char*)mask);

    wconv_k<<<wgrid, thr>>>(We_w, Whi + 0 * WSZ, Wlo + 0 * WSZ);
    wconv_k<<<wgrid, thr>>>(W_Q,  Whi + 1 * WSZ, Wlo + 1 * WSZ);
    wconv_k<<<wgrid, thr>>>(W_K,  Whi + 2 * WSZ, Wlo + 2 * WSZ);
    wconv_k<<<wgrid, thr>>>(W_V,  Whi + 3 * WSZ, Wlo + 3 * WSZ);
    wconv_k<<<wgrid, thr>>>(W_fc, Whi + 4 * WSZ, Wlo + 4 * WSZ);

    gemm_hmma_k<0><<<ggrid, thr, SM_TOTAL>>>(inter, Whi + 0 * WSZ, Wlo + 0 * WSZ, We_b, coefp);
    gemm_hmma_k<1><<<ggrid, thr, SM_TOTAL>>>(inQ,   Whi + 1 * WSZ, Wlo + 1 * WSZ, coefp, Qp);
    gemm_hmma_k<1><<<ggrid, thr, SM_TOTAL>>>(inK,   Whi + 2 * WSZ, Wlo + 2 * WSZ, coefp, Kp);
    gemm_hmma_k<2><<<ggrid, thr, SM_TOTAL>>>(inV,   Whi + 3 * WSZ, Wlo + 3 * WSZ, nullptr, Vp);

    attn_scores_k<<<sc_grid, thr>>>(Qp, Kp, dist, mask, P, rsp);
    attn_pv_k<<<pv_grid, thr>>>(P, Vp, rsp, ctxp, need_attn ? 1 : 0);

    gemm_hmma_k<3><<<ggrid, thr, SM_TOTAL>>>(ctxp, Whi + 4 * WSZ, Wlo + 4 * WSZ, inQ, out);
}